// round 11
// baseline (speedup 1.0000x reference)
#include <cuda_runtime.h>

#define LVL 32
#define WN  262144              // nodes per level, 2^18
#define NN  (LVL * WN)          // 8388608 total nodes
#define NT  256                 // 8 warps
#define HSZ 2048                // shared hash capacity (expected ~62 live keys)
#define QCAP 512                // queue capacity (expected ~16 published items)
#define TCAP 256                // terminal list capacity (expected ~31)
#define EVCAP 1024              // ev-record capacity (expected ~31)

// Global spill — only used on capacity overflow (never expected; fixed input).
__device__ long long d_spill_q[1 << 15];
__device__ int2      d_spill_term[1 << 15];
__device__ int4      d_spill_ev[1 << 15];

__device__ __forceinline__ void prefetch_l1(const void* p) {
    asm volatile("prefetch.global.L1 [%0];" :: "l"(p));
}

struct Smem {
    int qreserve;           // queue slots reserved
    int discovered;         // non-terminal nodes discovered (incl. root)
    int processed;          // non-terminal nodes fully expanded
    int evn, tcnt, h_root;
    int pad[26];
    int       key[HSZ];     // node id or -1
    long long vr[HSZ];      // (floatbits<<32) | readybit — published as one STS.64
    long long q[QCAP];      // (h<<32) | node — published as one STS.64; 0 = empty
    int2      term[TCAP];   // (node, h)
    int4      ev[EVCAP];    // (h_self, h0 | plusflag<<30, h1, 0)
};

__device__ __forceinline__ int hash_insert(int c, Smem* s, bool* inserted) {
    unsigned h = ((unsigned)c * 2654435761u) >> 21;   // top 11 bits
    while (true) {
        int prev = atomicCAS(&s->key[h], -1, c);
        if (prev == c)  { *inserted = false; break; }
        if (prev == -1) { *inserted = true;  break; }
        h = (h + 1) & (HSZ - 1);                       // linear probe
    }
    return (int)h;
}

__global__ __launch_bounds__(NT, 1)
void recnn_kernel(const float* __restrict__ values,
                  const int*   __restrict__ child_idx,   // [L-1, W, 2]
                  const int*   __restrict__ node_types,  // [L-1, W]
                  const float* __restrict__ w_term,
                  const float* __restrict__ w_plus,
                  const float* __restrict__ w_minus,
                  const float* __restrict__ w_final,
                  const float* __restrict__ b_final,
                  float*       __restrict__ out)
{
    extern __shared__ char smem_raw[];
    Smem* s = reinterpret_cast<Smem*>(smem_raw);
    const int tid = threadIdx.x;

    // ---- weight loads (latency hidden by init) ----
    const float wt  = w_term[0];
    const float wp0 = w_plus[0],  wp1 = w_plus[1];
    const float wm0 = w_minus[0], wm1 = w_minus[1];
    const float wf  = w_final[0], bf  = b_final[0];

    // ---- init: key = -1, vr = 0, q = 0, counters = 0 ----
    {
        int4* k4 = reinterpret_cast<int4*>(s->key);
        for (int i = tid; i < HSZ / 4; i += NT)
            k4[i] = make_int4(-1, -1, -1, -1);
        int4* z4 = reinterpret_cast<int4*>(s->vr);          // vr + q contiguous
        const int nz = (HSZ * 8 + QCAP * 8) / 16;
        for (int i = tid; i < nz; i += NT)
            z4[i] = make_int4(0, 0, 0, 0);
        if (tid == 0) {
            s->qreserve = 0; s->discovered = 1;             // root pre-discovered
            s->processed = 0; s->evn = 0; s->tcnt = 0;
        }
    }

    // ---- seed: thread 0 chases the root inline ----
    int cur = -1, curh = 0;
    if (tid == 0) {
        prefetch_l1(&child_idx[2 * (NN - 1 - WN)]);
        prefetch_l1(&node_types[NN - 1 - WN]);
        bool ins;
        curh = hash_insert(NN - 1, s, &ins);
        s->h_root = curh;
        cur = NN - 1;
    }
    __syncthreads();

    // -------- Phase A: multi-warp dataflow reachability ---------------------
    // Chain-critical path runs INLINE in one thread (no handoff); only the
    // second new child of a node is published for other warps to pick up.
    {
        int myNext = tid;
        for (;;) {
            if (cur >= 0) {
                int base = cur - WN;
                int2 c01 = *reinterpret_cast<const int2*>(&child_idx[2 * base]);
                int typ  = node_types[base];
                int hh[2];
                int nextc = -1, nexth = 0;
                #pragma unroll
                for (int j = 0; j < 2; j++) {
                    int c = j ? c01.y : c01.x;
                    bool ins;
                    int h = hash_insert(c, s, &ins);
                    hh[j] = h;
                    if (ins) {
                        if (c >= WN) {
                            prefetch_l1(&child_idx[2 * (c - WN)]);
                            prefetch_l1(&node_types[c - WN]);
                            atomicAdd(&s->discovered, 1);    // BEFORE publish
                            if (nextc < 0) { nextc = c; nexth = h; }
                            else {
                                long long pk = ((long long)h << 32) | (unsigned)c;
                                int pos = atomicAdd(&s->qreserve, 1);
                                if (pos < QCAP)
                                    *(volatile long long*)&s->q[pos] = pk;
                                else
                                    *(volatile long long*)&d_spill_q[pos - QCAP] = pk;
                            }
                        } else {
                            prefetch_l1(&values[c]);
                            int pos = atomicAdd(&s->tcnt, 1);
                            int2 te = make_int2(c, h);
                            if (pos < TCAP) s->term[pos] = te;
                            else            d_spill_term[pos - TCAP] = te;
                        }
                    }
                }
                int pos = atomicAdd(&s->evn, 1);
                int4 rec = make_int4(curh, hh[0] | ((typ == 1) ? (1 << 30) : 0), hh[1], 0);
                if (pos < EVCAP) s->ev[pos] = rec;
                else             d_spill_ev[pos - EVCAP] = rec;
                atomicAdd(&s->processed, 1);                 // last op of node body
                cur = nextc; curh = nexth;                   // chase inline
                continue;
            }
            // idle: poll my owned queue slot (uniform, cheap loop)
            int qr = *(volatile int*)&s->qreserve;
            if (myNext < qr) {
                long long pk;
                if (myNext < QCAP) pk = *(volatile long long*)&s->q[myNext];
                else               pk = *(volatile long long*)&d_spill_q[myNext - QCAP];
                if (pk != 0) {
                    cur  = (int)(pk & 0xffffffffll);
                    curh = (int)(pk >> 32);
                    myNext += NT;
                    continue;
                }
            }
            if (*(volatile int*)&s->processed == *(volatile int*)&s->discovered)
                break;
        }
    }
    __syncthreads();   // tcnt/evn/ev[] now final & visible

    // -------- terminal pass: parallel gather (L1/L2-warm) -------------------
    {
        int tn = s->tcnt;
        for (int i = tid; i < tn; i += NT) {
            int2 te = (i < TCAP) ? s->term[i] : d_spill_term[i - TCAP];
            float v = values[te.x] * wt;
            *(volatile long long*)&s->vr[te.y] =
                ((long long)(unsigned)__float_as_int(v) << 32) | 1ll;
        }
    }

    // -------- Phase B: multi-warp dataflow evaluation -----------------------
    {
        int evn = s->evn;
        int nMine = 0;
        for (int idx = tid; idx < evn; idx += NT) nMine++;
        unsigned long long doneMask = 0;
        int remaining = nMine;
        while (remaining) {
            for (int j = 0; j < nMine; j++) {
                if ((doneMask >> j) & 1ull) continue;
                int idx = tid + j * NT;
                int4 r = (idx < EVCAP) ? s->ev[idx] : d_spill_ev[idx - EVCAP];
                long long v0 = *(volatile long long*)&s->vr[r.y & 0x3fffffff];
                if (!(v0 & 1ll)) continue;
                long long v1 = *(volatile long long*)&s->vr[r.z];
                if (!(v1 & 1ll)) continue;
                float x0 = __int_as_float((int)(v0 >> 32));
                float x1 = __int_as_float((int)(v1 >> 32));
                float o = ((r.y >> 30) & 1) ? fmaf(x0, wp0, x1 * wp1)
                                            : fmaf(x0, wm0, x1 * wm1);
                *(volatile long long*)&s->vr[r.x] =
                    ((long long)(unsigned)__float_as_int(o) << 32) | 1ll;
                doneMask |= 1ull << j;
                remaining--;
            }
        }
    }
    __syncthreads();

    if (tid == 0) {
        long long vrk = *(volatile long long*)&s->vr[s->h_root];
        out[0] = __int_as_float((int)(vrk >> 32)) * wf + bf;
    }
}

extern "C" void kernel_launch(void* const* d_in, const int* in_sizes, int n_in,
                              void* d_out, int out_size)
{
    const float* values     = (const float*)d_in[0];
    const int*   child_idx  = (const int*)  d_in[1];
    const int*   node_types = (const int*)  d_in[2];
    const float* w_term     = (const float*)d_in[3];
    const float* w_plus     = (const float*)d_in[4];
    const float* w_minus    = (const float*)d_in[5];
    const float* w_final    = (const float*)d_in[6];
    const float* b_final    = (const float*)d_in[7];
    float* out = (float*)d_out;

    const int smem_bytes = (int)sizeof(Smem);   // ~47 KB
    cudaFuncSetAttribute(recnn_kernel,
                         cudaFuncAttributeMaxDynamicSharedMemorySize, smem_bytes);

    recnn_kernel<<<1, NT, smem_bytes>>>(values, child_idx, node_types,
                                        w_term, w_plus, w_minus,
                                        w_final, b_final, out);
}

// round 12
// speedup vs baseline: 1.0477x; 1.0477x over previous
#include <cuda_runtime.h>

#define LVL 32
#define WN  262144              // nodes per level, 2^18
#define NN  (LVL * WN)          // 8388608 total nodes
#define HSZ 1024                // shared hash capacity (expected ~62 live keys)
#define QCAP 1024               // wave-queue capacity (expected total ~31)
#define TCAP 256                // terminal list capacity (expected ~31)
#define EVCAP 1024              // ev-record capacity (expected ~31)
#define EVMAX 4                 // max ev records owned per lane (128 total cap in smem path)

// Global spill — only used on capacity overflow (never expected; fixed input).
__device__ int2 d_spill_q[1 << 15];
__device__ int2 d_spill_term[1 << 15];
__device__ int4 d_spill_ev[1 << 15];

__device__ __forceinline__ void prefetch_l1(const void* p) {
    asm volatile("prefetch.global.L1 [%0];" :: "l"(p));
}

struct Smem {
    int qtail, evn, tcnt, h_root;
    int pad[28];
    int       key[HSZ];     // node id or -1
    long long vr[HSZ];      // (floatbits<<32) | readybit
    int2      q[QCAP];      // (node, h_self) — non-terminals
    int2      term[TCAP];   // (node, h)
    int4      ev[EVCAP];    // (h_self, h0 | plusflag<<30, h1, 0)
};

__device__ __forceinline__ int hash_insert(int c, Smem* s, bool* inserted) {
    unsigned h = ((unsigned)c * 2654435761u) >> 22;   // top 10 bits
    while (true) {
        int prev = atomicCAS(&s->key[h], -1, c);
        if (prev == c)  { *inserted = false; break; }
        if (prev == -1) { *inserted = true;  break; }
        h = (h + 1) & (HSZ - 1);                       // linear probe
    }
    return (int)h;
}

__global__ __launch_bounds__(32, 1)
void recnn_kernel(const float* __restrict__ values,
                  const int*   __restrict__ child_idx,   // [L-1, W, 2]
                  const int*   __restrict__ node_types,  // [L-1, W]
                  const float* __restrict__ w_term,
                  const float* __restrict__ w_plus,
                  const float* __restrict__ w_minus,
                  const float* __restrict__ w_final,
                  const float* __restrict__ b_final,
                  float*       __restrict__ out)
{
    extern __shared__ char smem_raw[];
    Smem* s = reinterpret_cast<Smem*>(smem_raw);
    const int tid = threadIdx.x;

    // ---- weight loads (latency hidden by init) ----
    const float wt  = w_term[0];
    const float wp0 = w_plus[0],  wp1 = w_plus[1];
    const float wm0 = w_minus[0], wm1 = w_minus[1];
    const float wf  = w_final[0], bf  = b_final[0];

    // ---- init: key = -1 (4KB), vr = 0 (8KB), counters ----
    {
        int4* k4 = reinterpret_cast<int4*>(s->key);
        #pragma unroll
        for (int i = tid; i < HSZ / 4; i += 32)
            k4[i] = make_int4(-1, -1, -1, -1);
        int4* z4 = reinterpret_cast<int4*>(s->vr);
        #pragma unroll
        for (int i = tid; i < HSZ / 2; i += 32)
            z4[i] = make_int4(0, 0, 0, 0);
        if (tid == 0) { s->evn = 0; s->tcnt = 0; }
    }
    __syncwarp();

    // ---- seed root ----
    if (tid == 0) {
        bool ins;
        int h = hash_insert(NN - 1, s, &ins);
        s->h_root = h;
        s->q[0] = make_int2(NN - 1, h);
        s->qtail = 1;
        prefetch_l1(&child_idx[2 * (NN - 1 - WN)]);
        prefetch_l1(&node_types[NN - 1 - WN]);
    }

    // -------- Phase A: wave-queue BFS (proven R8 structure) -----------------
    int lo = 0;
    while (true) {
        __syncwarp();
        int hi = s->qtail;
        if (hi == lo) break;
        // pair-lane: lanes 2i,2i+1 handle queue entry i's two children
        for (int i = lo + (tid >> 1); i < hi; i += 16) {
            int2 e   = (i < QCAP) ? s->q[i] : d_spill_q[i - QCAP];
            int base = e.x - WN;                       // node - WN
            int2 c01 = *reinterpret_cast<const int2*>(&child_idx[2 * base]);
            int typ  = node_types[base];
            int c = (tid & 1) ? c01.y : c01.x;

            bool ins;
            int h = hash_insert(c, s, &ins);
            if (ins) {
                if (c >= WN) {
                    prefetch_l1(&child_idx[2 * (c - WN)]);
                    prefetch_l1(&node_types[c - WN]);
                    int pos = atomicAdd(&s->qtail, 1);
                    int2 qe = make_int2(c, h);
                    if (pos < QCAP) s->q[pos] = qe;
                    else            d_spill_q[pos - QCAP] = qe;
                } else {
                    prefetch_l1(&values[c]);           // warm for terminal pass
                    int pos = atomicAdd(&s->tcnt, 1);
                    int2 te = make_int2(c, h);
                    if (pos < TCAP) s->term[pos] = te;
                    else            d_spill_term[pos - TCAP] = te;
                }
            }
            // exchange sibling hash slots within the pair
            unsigned pmask = 3u << (tid & 30);
            int ho = __shfl_xor_sync(pmask, h, 1);
            if (!(tid & 1)) {
                int pos = atomicAdd(&s->evn, 1);
                int4 rec = make_int4(e.y, h | ((typ == 1) ? (1 << 30) : 0), ho, 0);
                if (pos < EVCAP) s->ev[pos] = rec;
                else             d_spill_ev[pos - EVCAP] = rec;
            }
        }
        lo = hi;
    }

    // -------- terminal pass: parallel gather (L1-warm from prefetch) --------
    {
        int tn = s->tcnt;
        for (int i = tid; i < tn; i += 32) {
            int2 te = (i < TCAP) ? s->term[i] : d_spill_term[i - TCAP];
            float v = values[te.x] * wt;
            s->vr[te.y] = ((long long)(unsigned)__float_as_int(v) << 32) | 1ll;
        }
    }
    __syncwarp();

    // -------- Phase B: dependency-depth dataflow rounds (converged warp) ----
    {
        int evn = s->evn;
        int4 rec[EVMAX];
        unsigned pend = 0;
        int nMine = 0;
        #pragma unroll
        for (int k = 0; k < EVMAX; k++) {
            int idx = tid + 32 * k;
            if (idx < evn) {
                rec[k] = (idx < EVCAP) ? s->ev[idx] : d_spill_ev[idx - EVCAP];
                pend |= 1u << k;
                nMine = k + 1;
            }
        }
        // spill beyond EVMAX*32 records handled in the slow tail below (never expected)
        while (__ballot_sync(0xffffffffu, pend != 0)) {
            #pragma unroll
            for (int k = 0; k < EVMAX; k++) {
                if (!((pend >> k) & 1u)) continue;
                int4 r = rec[k];
                long long v0 = s->vr[r.y & 0x3fffffff];
                if (!(v0 & 1ll)) continue;
                long long v1 = s->vr[r.z];
                if (!(v1 & 1ll)) continue;
                float x0 = __int_as_float((int)(v0 >> 32));
                float x1 = __int_as_float((int)(v1 >> 32));
                float o = ((r.y >> 30) & 1) ? fmaf(x0, wp0, x1 * wp1)
                                            : fmaf(x0, wm0, x1 * wm1);
                s->vr[r.x] = ((long long)(unsigned)__float_as_int(o) << 32) | 1ll;
                pend &= ~(1u << k);
            }
            __syncwarp();
        }
        // slow tail for absurd spill case (evn > EVMAX*32): level-free sweep
        if (evn > EVMAX * 32) {
            for (;;) {
                int done = 1;
                for (int idx = EVMAX * 32 + tid; idx < evn; idx += 32) {
                    int4 r = (idx < EVCAP) ? s->ev[idx] : d_spill_ev[idx - EVCAP];
                    if (s->vr[r.x] & 1ll) continue;
                    long long v0 = s->vr[r.y & 0x3fffffff];
                    long long v1 = s->vr[r.z];
                    if (!(v0 & 1ll) || !(v1 & 1ll)) { done = 0; continue; }
                    float x0 = __int_as_float((int)(v0 >> 32));
                    float x1 = __int_as_float((int)(v1 >> 32));
                    float o = ((r.y >> 30) & 1) ? fmaf(x0, wp0, x1 * wp1)
                                                : fmaf(x0, wm0, x1 * wm1);
                    s->vr[r.x] = ((long long)(unsigned)__float_as_int(o) << 32) | 1ll;
                }
                __syncwarp();
                if (__all_sync(0xffffffffu, done)) break;
            }
        }
    }
    __syncwarp();

    if (tid == 0) {
        long long vrk = s->vr[s->h_root];
        out[0] = __int_as_float((int)(vrk >> 32)) * wf + bf;
    }
}

extern "C" void kernel_launch(void* const* d_in, const int* in_sizes, int n_in,
                              void* d_out, int out_size)
{
    const float* values     = (const float*)d_in[0];
    const int*   child_idx  = (const int*)  d_in[1];
    const int*   node_types = (const int*)  d_in[2];
    const float* w_term     = (const float*)d_in[3];
    const float* w_plus     = (const float*)d_in[4];
    const float* w_minus    = (const float*)d_in[5];
    const float* w_final    = (const float*)d_in[6];
    const float* b_final    = (const float*)d_in[7];
    float* out = (float*)d_out;

    const int smem_bytes = (int)sizeof(Smem);   // ~33 KB
    cudaFuncSetAttribute(recnn_kernel,
                         cudaFuncAttributeMaxDynamicSharedMemorySize, smem_bytes);

    recnn_kernel<<<1, 32, smem_bytes>>>(values, child_idx, node_types,
                                        w_term, w_plus, w_minus,
                                        w_final, b_final, out);
}

// round 13
// speedup vs baseline: 1.5731x; 1.5015x over previous
#include <cuda_runtime.h>

#define LVL 32
#define WN  262144              // nodes per level, 2^18
#define NN  (LVL * WN)          // 8388608 total nodes
#define SCAP 256                // per-level ev capacity (expected max ~16)
#define QCAP 2048               // wave-queue capacity (expected total ~31)
#define HSZ 2048                // shared hash capacity (expected ~62 live keys)
#define TCAP 256                // terminal list capacity (expected ~31)

// Spill storage — only used on capacity overflow (never expected; fixed input).
__device__ int2 d_spill_q[1 << 16];
__device__ int2 d_spill_term[1 << 15];
__device__ int4 d_spill_ev[LVL][1 << 13];

__device__ __forceinline__ void prefetch_l1(const void* p) {
    asm volatile("prefetch.global.L1 [%0];" :: "l"(p));
}

struct Smem {
    int   cnt[LVL];             // per-level ev counts
    int   qtail;
    int   tcnt;                 // terminal count
    int   h_root;
    int   pad[29];
    int   key[HSZ];             // node id or -1
    float fval[HSZ];            // value of node key[h]
    int2  q[QCAP];              // wave queue: (node, h_self), non-terminals only
    int2  term[TCAP];           // terminals: (node, h)
    int4  ev[LVL][SCAP];        // (h_self, h0 | plusflag<<30, h1, 0)
};

// Claim-or-find: returns hash slot; *inserted = true iff this call claimed it.
__device__ __forceinline__ int hash_insert(int c, Smem* s, bool* inserted) {
    unsigned h = ((unsigned)c * 2654435761u) >> 21;   // top 11 bits
    while (true) {
        int prev = atomicCAS(&s->key[h], -1, c);
        if (prev == c)  { *inserted = false; break; }
        if (prev == -1) { *inserted = true;  break; }
        h = (h + 1) & (HSZ - 1);                       // linear probe
    }
    return (int)h;
}

__global__ __launch_bounds__(32, 1)
void recnn_kernel(const float* __restrict__ values,
                  const int*   __restrict__ child_idx,   // [L-1, W, 2]
                  const int*   __restrict__ node_types,  // [L-1, W]
                  const float* __restrict__ w_term,
                  const float* __restrict__ w_plus,
                  const float* __restrict__ w_minus,
                  const float* __restrict__ w_final,
                  const float* __restrict__ b_final,
                  float*       __restrict__ out)
{
    extern __shared__ char smem_raw[];
    Smem* s = reinterpret_cast<Smem*>(smem_raw);
    const int tid = threadIdx.x;

    // ---- issue weight loads immediately (latency hidden by init) ----
    const float wt  = w_term[0];
    const float wp0 = w_plus[0],  wp1 = w_plus[1];
    const float wm0 = w_minus[0], wm1 = w_minus[1];
    const float wf  = w_final[0], bf  = b_final[0];

    // ---- init hash keys to -1, counters to 0 ----
    {
        int4* k4 = reinterpret_cast<int4*>(s->key);
        #pragma unroll
        for (int i = tid; i < HSZ / 4; i += 32)
            k4[i] = make_int4(-1, -1, -1, -1);
        s->cnt[tid] = 0;                                // tid < 32 == LVL
        if (tid == 0) { s->qtail = 0; s->tcnt = 0; }
    }
    __syncwarp();

    // ---- seed root ----
    if (tid == 0) {
        bool ins;
        int h = hash_insert(NN - 1, s, &ins);
        s->h_root = h;
        s->q[0] = make_int2(NN - 1, h);
        s->qtail = 1;
        prefetch_l1(&child_idx[2 * (NN - 1 - WN)]);
        prefetch_l1(&node_types[NN - 1 - WN]);
    }

    // -------- Phase A: wave-queue BFS (order-free reachability) ------------
    // Shared node-expansion body; the queue READ is branch-separated so the
    // fast path contains NO global loads (ternary reads can compile to
    // dual-load + SEL, putting a cold-DRAM spill load on the chain).
    auto expand = [&](int2 e) {
        int base = e.x - WN;                           // node - WN
        int2 c01 = *reinterpret_cast<const int2*>(&child_idx[2 * base]);
        int typ  = node_types[base];
        int c = (tid & 1) ? c01.y : c01.x;

        bool ins;
        int h = hash_insert(c, s, &ins);
        if (ins) {
            if (c >= WN) {
                prefetch_l1(&child_idx[2 * (c - WN)]);
                prefetch_l1(&node_types[c - WN]);
                int pos = atomicAdd(&s->qtail, 1);
                int2 qe = make_int2(c, h);
                if (pos < QCAP) s->q[pos] = qe;
                else            d_spill_q[pos - QCAP] = qe;
            } else {
                prefetch_l1(&values[c]);               // warm for terminal pass
                int pos = atomicAdd(&s->tcnt, 1);
                int2 te = make_int2(c, h);
                if (pos < TCAP) s->term[pos] = te;
                else            d_spill_term[pos - TCAP] = te;
            }
        }
        // exchange sibling hash slots within the pair
        unsigned pmask = 3u << (tid & 30);
        int ho = __shfl_xor_sync(pmask, h, 1);
        if (!(tid & 1)) {
            int l   = e.x >> 18;                       // parent's level
            int pos = atomicAdd(&s->cnt[l], 1);
            int4 rec = make_int4(e.y, h | ((typ == 1) ? (1 << 30) : 0), ho, 0);
            if (pos < SCAP) s->ev[l][pos] = rec;
            else            d_spill_ev[l][pos - SCAP] = rec;
        }
    };

    int lo = 0;
    while (true) {
        __syncwarp();
        int hi = s->qtail;
        if (hi == lo) break;
        if (hi <= QCAP) {                              // fast path: smem-only reads
            for (int i = lo + (tid >> 1); i < hi; i += 16)
                expand(s->q[i]);
        } else {                                       // slow path (never expected)
            for (int i = lo + (tid >> 1); i < hi; i += 16) {
                int2 e;
                if (i < QCAP) e = s->q[i];
                else          e = d_spill_q[i - QCAP];
                expand(e);
            }
        }
        lo = hi;
    }

    // -------- terminal pass: one parallel gather (L1-warm) ------------------
    {
        int tn = s->tcnt;
        if (tn <= TCAP) {                              // fast path: smem-only reads
            for (int i = tid; i < tn; i += 32) {
                int2 te = s->term[i];
                s->fval[te.y] = values[te.x] * wt;
            }
        } else {
            for (int i = tid; i < tn; i += 32) {
                int2 te;
                if (i < TCAP) te = s->term[i];
                else          te = d_spill_term[i - TCAP];
                s->fval[te.y] = values[te.x] * wt;
            }
        }
    }

    // -------- Phase B: bottom-up evaluation over non-empty levels ----------
    unsigned m;
    {
        int myc = s->cnt[tid];                         // cnt[0] == 0 always
        m = __ballot_sync(0xffffffffu, myc != 0);
    }
    while (m) {
        int lb = __ffs(m) - 1;
        m &= m - 1;
        __syncwarp();
        int n = s->cnt[lb];
        if (n <= SCAP) {                               // fast path: smem-only reads
            for (int i = tid; i < n; i += 32) {
                int4 r  = s->ev[lb][i];
                float x0 = s->fval[r.y & 0x3fffffff];
                float x1 = s->fval[r.z];
                s->fval[r.x] = ((r.y >> 30) & 1) ? fmaf(x0, wp0, x1 * wp1)
                                                 : fmaf(x0, wm0, x1 * wm1);
            }
        } else {
            for (int i = tid; i < n; i += 32) {
                int4 r;
                if (i < SCAP) r = s->ev[lb][i];
                else          r = d_spill_ev[lb][i - SCAP];
                float x0 = s->fval[r.y & 0x3fffffff];
                float x1 = s->fval[r.z];
                s->fval[r.x] = ((r.y >> 30) & 1) ? fmaf(x0, wp0, x1 * wp1)
                                                 : fmaf(x0, wm0, x1 * wm1);
            }
        }
    }
    __syncwarp();

    if (tid == 0)
        out[0] = s->fval[s->h_root] * wf + bf;
}

extern "C" void kernel_launch(void* const* d_in, const int* in_sizes, int n_in,
                              void* d_out, int out_size)
{
    const float* values     = (const float*)d_in[0];
    const int*   child_idx  = (const int*)  d_in[1];
    const int*   node_types = (const int*)  d_in[2];
    const float* w_term     = (const float*)d_in[3];
    const float* w_plus     = (const float*)d_in[4];
    const float* w_minus    = (const float*)d_in[5];
    const float* w_final    = (const float*)d_in[6];
    const float* b_final    = (const float*)d_in[7];
    float* out = (float*)d_out;

    const int smem_bytes = (int)sizeof(Smem);
    cudaFuncSetAttribute(recnn_kernel,
                         cudaFuncAttributeMaxDynamicSharedMemorySize, smem_bytes);

    recnn_kernel<<<1, 32, smem_bytes>>>(values, child_idx, node_types,
                                        w_term, w_plus, w_minus,
                                        w_final, b_final, out);
}

// round 15
// speedup vs baseline: 1.9375x; 1.2316x over previous
#include <cuda_runtime.h>

#define LVL 32
#define WN  262144              // nodes per level, 2^18
#define NN  (LVL * WN)          // 8388608 total nodes
#define QCAP 4096               // wave-queue capacity (expected total ~63 items)

// Global spill — only used on capacity overflow (never expected; fixed input).
__device__ int2 d_spill_q[1 << 16];

__device__ __forceinline__ void prefetch_l1(const void* p) {
    asm volatile("prefetch.global.L1 [%0];" :: "l"(p));
}

struct Smem {
    int  qtail;
    int  pad[31];
    int2 q[QCAP];               // (node, float-bits multiplier)
};

__global__ __launch_bounds__(32, 1)
void recnn_kernel(const float* __restrict__ values,
                  const int*   __restrict__ child_idx,   // [L-1, W, 2]
                  const int*   __restrict__ node_types,  // [L-1, W]
                  const float* __restrict__ w_term,
                  const float* __restrict__ w_plus,
                  const float* __restrict__ w_minus,
                  const float* __restrict__ w_final,
                  const float* __restrict__ b_final,
                  float*       __restrict__ out)
{
    extern __shared__ char smem_raw[];
    Smem* s = reinterpret_cast<Smem*>(smem_raw);
    const int tid = threadIdx.x;

    // ---- weight loads (latency hidden behind seeding) ----
    const float wp0 = w_plus[0],  wp1 = w_plus[1];
    const float wm0 = w_minus[0], wm1 = w_minus[1];

    // ---- seed root with multiplier 1.0 ----
    if (tid == 0) {
        s->q[0] = make_int2(NN - 1, __float_as_int(1.0f));
        s->qtail = 1;
        prefetch_l1(&child_idx[2 * (NN - 1 - WN)]);
        prefetch_l1(&node_types[NN - 1 - WN]);
    }

    float acc = 0.0f;           // per-lane terminal accumulator

    // push helper: non-terminal -> queue; terminal -> accumulate m * value
    auto push = [&](int c, float m) {
        if (c >= WN) {
            prefetch_l1(&child_idx[2 * (c - WN)]);     // warm next wave
            prefetch_l1(&node_types[c - WN]);
            int pos = atomicAdd(&s->qtail, 1);
            int2 qe = make_int2(c, __float_as_int(m));
            if (pos < QCAP) s->q[pos] = qe;
            else            d_spill_q[pos - QCAP] = qe;
        } else {
            acc = fmaf(m, values[c], acc);             // latency hidden till reduce
        }
    };

    auto expand = [&](int2 e) {
        int   base = e.x - WN;                         // node - WN
        float m    = __int_as_float(e.y);
        int2  c01  = *reinterpret_cast<const int2*>(&child_idx[2 * base]);
        int   typ  = node_types[base];
        float w0 = (typ == 1) ? wp0 : wm0;
        float w1 = (typ == 1) ? wp1 : wm1;
        push(c01.x, m * w0);
        push(c01.y, m * w1);
    };

    // -------- single pass: coefficient-propagating wave BFS -----------------
    int lo = 0;
    while (true) {
        __syncwarp();
        int hi = s->qtail;
        if (hi == lo) break;
        if (hi <= QCAP) {                              // fast path: smem-only reads
            for (int i = lo + tid; i < hi; i += 32)
                expand(s->q[i]);
        } else {                                       // spill path (never expected)
            for (int i = lo + tid; i < hi; i += 32) {
                int2 e;
                if (i < QCAP) e = s->q[i];
                else          e = d_spill_q[i - QCAP];
                expand(e);
            }
        }
        lo = hi;
    }

    // -------- warp reduction + final affine ---------------------------------
    #pragma unroll
    for (int off = 16; off; off >>= 1)
        acc += __shfl_down_sync(0xffffffffu, acc, off);

    if (tid == 0)
        out[0] = acc * w_term[0] * w_final[0] + b_final[0];
}

extern "C" void kernel_launch(void* const* d_in, const int* in_sizes, int n_in,
                              void* d_out, int out_size)
{
    const float* values     = (const float*)d_in[0];
    const int*   child_idx  = (const int*)  d_in[1];
    const int*   node_types = (const int*)  d_in[2];
    const float* w_term     = (const float*)d_in[3];
    const float* w_plus     = (const float*)d_in[4];
    const float* w_minus    = (const float*)d_in[5];
    const float* w_final    = (const float*)d_in[6];
    const float* b_final    = (const float*)d_in[7];
    float* out = (float*)d_out;

    const int smem_bytes = (int)sizeof(Smem);   // ~33 KB
    cudaFuncSetAttribute(recnn_kernel,
                         cudaFuncAttributeMaxDynamicSharedMemorySize, smem_bytes);

    recnn_kernel<<<1, 32, smem_bytes>>>(values, child_idx, node_types,
                                        w_term, w_plus, w_minus,
                                        w_final, b_final, out);
}